// round 3
// baseline (speedup 1.0000x reference)
#include <cuda_runtime.h>
#include <cuda_bf16.h>

// Problem constants (fixed by the reference setup)
#define BDIM 2
#define TDIM 2048
#define CDIM 1024
#define HN   16
#define HD   64
#define MROWS (BDIM * TDIM)   // 4096
#define NQKV  (3 * CDIM)      // 3072
#define KDEPTH CDIM           // 1024

// Scratch (static device globals — allocation-free)
__device__ __align__(16) float g_Q[BDIM * HN * TDIM * HD];   // (B,H,T,hd)
__device__ __align__(16) float g_K[BDIM * HN * TDIM * HD];
__device__ __align__(16) float g_V[BDIM * HN * TDIM * HD];
__device__ __align__(16) float g_att[MROWS * CDIM];          // (B,T,C)

// ---------------------------------------------------------------------------
// GEMM 1: qkv = x @ Wqkv + bqkv ; scatter to Q/K/V in (B,H,T,hd) layout.
// 64x64 block tile, BK=16, 256 threads, 4x4 register micro-tile.
// ---------------------------------------------------------------------------
__global__ void __launch_bounds__(256) gemm_qkv_kernel(
    const float* __restrict__ A,      // x       [4096, 1024]
    const float* __restrict__ W,      // Wqkv    [1024, 3072]
    const float* __restrict__ bias)   // bqkv    [3072]
{
    __shared__ __align__(16) float As[16][64];   // A transposed: [k][m]
    __shared__ __align__(16) float Bs[16][64];   // [k][n]

    const int tid = threadIdx.x;
    const int m0 = blockIdx.y * 64;
    const int n0 = blockIdx.x * 64;
    const int tm0 = (tid >> 4) * 4;
    const int tn0 = (tid & 15) * 4;
    const int arow = tid >> 2, ak = (tid & 3) * 4;   // A tile loader
    const int brow = tid >> 4, bcol = (tid & 15) * 4; // B tile loader

    float acc[4][4] = {};

    for (int k0 = 0; k0 < KDEPTH; k0 += 16) {
        float4 av = *(const float4*)&A[(m0 + arow) * KDEPTH + k0 + ak];
        As[ak + 0][arow] = av.x;
        As[ak + 1][arow] = av.y;
        As[ak + 2][arow] = av.z;
        As[ak + 3][arow] = av.w;
        *(float4*)&Bs[brow][bcol] = *(const float4*)&W[(k0 + brow) * NQKV + n0 + bcol];
        __syncthreads();
#pragma unroll
        for (int k = 0; k < 16; k++) {
            float4 a4 = *(const float4*)&As[k][tm0];
            float4 b4 = *(const float4*)&Bs[k][tn0];
            float a[4] = {a4.x, a4.y, a4.z, a4.w};
            float b[4] = {b4.x, b4.y, b4.z, b4.w};
#pragma unroll
            for (int i = 0; i < 4; i++)
#pragma unroll
                for (int j = 0; j < 4; j++)
                    acc[i][j] += a[i] * b[j];
        }
        __syncthreads();
    }

    // Epilogue: add bias and scatter column n -> (head, which, d)
#pragma unroll
    for (int i = 0; i < 4; i++) {
        int m = m0 + tm0 + i;
        int bb = m >> 11;        // m / 2048
        int t  = m & 2047;
#pragma unroll
        for (int j = 0; j < 4; j++) {
            int n = n0 + tn0 + j;
            float c = acc[i][j] + bias[n];
            int h = n / 192;
            int r = n - h * 192;
            int which = r >> 6;
            int d = r & 63;
            int idx = (((bb * HN + h) * TDIM) + t) * HD + d;
            if (which == 0)      g_Q[idx] = c;
            else if (which == 1) g_K[idx] = c;
            else                 g_V[idx] = c;
        }
    }
}

// ---------------------------------------------------------------------------
// Flash attention (fp32, causal). One block per (q-tile of 64, head, batch).
// 256 threads, 4x4 register tiles for both S = Q K^T and O += P V.
// Online softmax per row; KsT buffer reused for P to stay at 48KB static smem.
// ---------------------------------------------------------------------------
__global__ void __launch_bounds__(256) attn_kernel()
{
    __shared__ __align__(16) float QsT[64][64];  // [d][qrow]
    __shared__ __align__(16) float KsT[64][64];  // [d][kcol]; reused as Ps[qrow][kcol]
    __shared__ __align__(16) float Vs[64][64];   // [kcol][d]

    const int tid = threadIdx.x;
    const int tx = tid & 15;   // 16 cols of the thread grid
    const int ty = tid >> 4;   // 16 rows
    const int qtile = blockIdx.x;
    const int h = blockIdx.y;
    const int b = blockIdx.z;

    const float* Qb = g_Q + (((b * HN + h) * TDIM) + qtile * 64) * HD;
    const float* Kb = g_K + ((b * HN + h) * TDIM) * HD;
    const float* Vb = g_V + ((b * HN + h) * TDIM) * HD;

    // Load Q tile transposed into QsT[d][qrow]
    {
        int row = tid >> 2;
        int d0 = (tid & 3) * 16;
#pragma unroll
        for (int v = 0; v < 4; v++) {
            float4 q4 = *(const float4*)&Qb[row * HD + d0 + v * 4];
            QsT[d0 + v * 4 + 0][row] = q4.x;
            QsT[d0 + v * 4 + 1][row] = q4.y;
            QsT[d0 + v * 4 + 2][row] = q4.z;
            QsT[d0 + v * 4 + 3][row] = q4.w;
        }
    }

    float m_i[4], l_i[4], o_acc[4][4];
#pragma unroll
    for (int i = 0; i < 4; i++) {
        m_i[i] = -1e30f;
        l_i[i] = 0.f;
#pragma unroll
        for (int j = 0; j < 4; j++) o_acc[i][j] = 0.f;
    }

    float (*Ps)[64] = (float (*)[64])KsT;  // alias: P overwrites K tile

    for (int kt = 0; kt <= qtile; kt++) {
        __syncthreads();  // previous O-GEMM reads of Ps/Vs complete

        // Load K tile transposed + V tile natural
        {
            int row = tid >> 2;
            int d0 = (tid & 3) * 16;
            const float* Kp = Kb + (kt * 64 + row) * HD;
            const float* Vp = Vb + (kt * 64 + row) * HD;
#pragma unroll
            for (int v = 0; v < 4; v++) {
                float4 k4 = *(const float4*)&Kp[d0 + v * 4];
                KsT[d0 + v * 4 + 0][row] = k4.x;
                KsT[d0 + v * 4 + 1][row] = k4.y;
                KsT[d0 + v * 4 + 2][row] = k4.z;
                KsT[d0 + v * 4 + 3][row] = k4.w;
                *(float4*)&Vs[row][d0 + v * 4] = *(const float4*)&Vp[d0 + v * 4];
            }
        }
        __syncthreads();  // tiles ready

        // S = Q K^T   (64x64x64), 4x4 per thread
        float s[4][4] = {};
#pragma unroll
        for (int d = 0; d < 64; d++) {
            float4 a4 = *(const float4*)&QsT[d][ty * 4];
            float4 b4 = *(const float4*)&KsT[d][tx * 4];
            float a[4] = {a4.x, a4.y, a4.z, a4.w};
            float bb[4] = {b4.x, b4.y, b4.z, b4.w};
#pragma unroll
            for (int i = 0; i < 4; i++)
#pragma unroll
                for (int j = 0; j < 4; j++)
                    s[i][j] += a[i] * bb[j];
        }

        __syncthreads();  // all KsT reads done before P overwrites it

        // Scale, causal mask, online softmax update
        const float sc = 0.125f;  // 1/sqrt(64)
#pragma unroll
        for (int i = 0; i < 4; i++) {
            int qg = qtile * 64 + ty * 4 + i;
#pragma unroll
            for (int j = 0; j < 4; j++) {
                int kg = kt * 64 + tx * 4 + j;
                s[i][j] = (kg <= qg) ? s[i][j] * sc : -1e30f;
            }
            float rm = fmaxf(fmaxf(s[i][0], s[i][1]), fmaxf(s[i][2], s[i][3]));
            rm = fmaxf(rm, __shfl_xor_sync(0xffffffffu, rm, 1));
            rm = fmaxf(rm, __shfl_xor_sync(0xffffffffu, rm, 2));
            rm = fmaxf(rm, __shfl_xor_sync(0xffffffffu, rm, 4));
            rm = fmaxf(rm, __shfl_xor_sync(0xffffffffu, rm, 8));
            float mnew = fmaxf(m_i[i], rm);
            float alpha = __expf(m_i[i] - mnew);
            m_i[i] = mnew;
            float rs = 0.f;
#pragma unroll
            for (int j = 0; j < 4; j++) {
                float p = __expf(s[i][j] - mnew);
                s[i][j] = p;
                rs += p;
            }
            rs += __shfl_xor_sync(0xffffffffu, rs, 1);
            rs += __shfl_xor_sync(0xffffffffu, rs, 2);
            rs += __shfl_xor_sync(0xffffffffu, rs, 4);
            rs += __shfl_xor_sync(0xffffffffu, rs, 8);
            l_i[i] = l_i[i] * alpha + rs;
#pragma unroll
            for (int j = 0; j < 4; j++) o_acc[i][j] *= alpha;
        }

        // Write P into (former K) smem
#pragma unroll
        for (int i = 0; i < 4; i++)
            *(float4*)&Ps[ty * 4 + i][tx * 4] =
                make_float4(s[i][0], s[i][1], s[i][2], s[i][3]);
        __syncthreads();  // P ready

        // O += P @ V   (64x64x64), contraction over k-col
#pragma unroll
        for (int kk = 0; kk < 64; kk++) {
            float4 v4 = *(const float4*)&Vs[kk][tx * 4];
            float a0 = Ps[ty * 4 + 0][kk];
            float a1 = Ps[ty * 4 + 1][kk];
            float a2 = Ps[ty * 4 + 2][kk];
            float a3 = Ps[ty * 4 + 3][kk];
            o_acc[0][0] += a0 * v4.x; o_acc[0][1] += a0 * v4.y;
            o_acc[0][2] += a0 * v4.z; o_acc[0][3] += a0 * v4.w;
            o_acc[1][0] += a1 * v4.x; o_acc[1][1] += a1 * v4.y;
            o_acc[1][2] += a1 * v4.z; o_acc[1][3] += a1 * v4.w;
            o_acc[2][0] += a2 * v4.x; o_acc[2][1] += a2 * v4.y;
            o_acc[2][2] += a2 * v4.z; o_acc[2][3] += a2 * v4.w;
            o_acc[3][0] += a3 * v4.x; o_acc[3][1] += a3 * v4.y;
            o_acc[3][2] += a3 * v4.z; o_acc[3][3] += a3 * v4.w;
        }
    }

    // Normalize and write to g_att in (B,T,C) layout
#pragma unroll
    for (int i = 0; i < 4; i++) {
        float inv = 1.0f / l_i[i];
        int t = qtile * 64 + ty * 4 + i;
        float4 o4 = make_float4(o_acc[i][0] * inv, o_acc[i][1] * inv,
                                o_acc[i][2] * inv, o_acc[i][3] * inv);
        *(float4*)&g_att[(b * TDIM + t) * CDIM + h * HD + tx * 4] = o4;
    }
}

// ---------------------------------------------------------------------------
// GEMM 2: out = att @ Wproj + bproj   [4096,1024] x [1024,1024]
// ---------------------------------------------------------------------------
__global__ void __launch_bounds__(256) gemm_proj_kernel(
    const float* __restrict__ W,      // Wproj [1024, 1024]
    const float* __restrict__ bias,   // bproj [1024]
    float* __restrict__ out)          // [4096, 1024]
{
    __shared__ __align__(16) float As[16][64];
    __shared__ __align__(16) float Bs[16][64];

    const int tid = threadIdx.x;
    const int m0 = blockIdx.y * 64;
    const int n0 = blockIdx.x * 64;
    const int tm0 = (tid >> 4) * 4;
    const int tn0 = (tid & 15) * 4;
    const int arow = tid >> 2, ak = (tid & 3) * 4;
    const int brow = tid >> 4, bcol = (tid & 15) * 4;

    float acc[4][4] = {};

    for (int k0 = 0; k0 < KDEPTH; k0 += 16) {
        float4 av = *(const float4*)&g_att[(m0 + arow) * KDEPTH + k0 + ak];
        As[ak + 0][arow] = av.x;
        As[ak + 1][arow] = av.y;
        As[ak + 2][arow] = av.z;
        As[ak + 3][arow] = av.w;
        *(float4*)&Bs[brow][bcol] = *(const float4*)&W[(k0 + brow) * CDIM + n0 + bcol];
        __syncthreads();
#pragma unroll
        for (int k = 0; k < 16; k++) {
            float4 a4 = *(const float4*)&As[k][tm0];
            float4 b4 = *(const float4*)&Bs[k][tn0];
            float a[4] = {a4.x, a4.y, a4.z, a4.w};
            float b[4] = {b4.x, b4.y, b4.z, b4.w};
#pragma unroll
            for (int i = 0; i < 4; i++)
#pragma unroll
                for (int j = 0; j < 4; j++)
                    acc[i][j] += a[i] * b[j];
        }
        __syncthreads();
    }

#pragma unroll
    for (int i = 0; i < 4; i++) {
        int m = m0 + tm0 + i;
#pragma unroll
        for (int j = 0; j < 4; j++) {
            int n = n0 + tn0 + j;
            out[m * CDIM + n] = acc[i][j] + bias[n];
        }
    }
}

// ---------------------------------------------------------------------------
extern "C" void kernel_launch(void* const* d_in, const int* in_sizes, int n_in,
                              void* d_out, int out_size)
{
    const float* x     = (const float*)d_in[0];
    const float* Wqkv  = (const float*)d_in[1];
    const float* bqkv  = (const float*)d_in[2];
    const float* Wproj = (const float*)d_in[3];
    const float* bproj = (const float*)d_in[4];
    float* out = (float*)d_out;

    dim3 g1(NQKV / 64, MROWS / 64);      // 48 x 64
    gemm_qkv_kernel<<<g1, 256>>>(x, Wqkv, bqkv);

    dim3 ga(TDIM / 64, HN, BDIM);        // 32 x 16 x 2
    attn_kernel<<<ga, 256>>>();

    dim3 g2(CDIM / 64, MROWS / 64);      // 16 x 64
    gemm_proj_kernel<<<g2, 256>>>(Wproj, bproj, out);
}